// round 1
// baseline (speedup 1.0000x reference)
#include <cuda_runtime.h>
#include <math.h>

// Problem constants
#define PB   128
#define PU   4
#define PNBS 64
#define PS   408

constexpr int S4   = PS / 4;                       // 102
constexpr int TOT  = PB * PU * PNBS * PS;          // 13,369,344
constexpr int TOT4 = TOT / 4;                      // 3,342,336
constexpr int AT   = PB * PU * PS;                 // 208,896
constexpr int AT4  = AT / 4;                       // 52,224

// Global double accumulators (no device alloc allowed; __device__ globals OK)
__device__ double g_recv;
__device__ double g_em_rad;
__device__ double g_em_at;

__global__ void prism_init_kernel() {
    g_recv   = 0.0;
    g_em_rad = 0.0;
    g_em_at  = 0.0;
}

__device__ __forceinline__ float warp_reduce(float v) {
    #pragma unroll
    for (int off = 16; off > 0; off >>= 1)
        v += __shfl_down_sync(0xffffffffu, v, off);
    return v;
}

__global__ __launch_bounds__(256, 8)
void prism_main_kernel(const float4* __restrict__ a_re_g,
                       const float4* __restrict__ a_im_g,
                       const float4* __restrict__ r_re_g,
                       const float4* __restrict__ r_im_g,
                       const float4* __restrict__ t_re_g,
                       const float4* __restrict__ t_im_g,
                       const float4* __restrict__ w_g) {
    const int tid    = blockIdx.x * blockDim.x + threadIdx.x;
    const int stride = gridDim.x * blockDim.x;

    float recv = 0.0f;   // sum(se * w)
    float emr  = 0.0f;   // sum(relu(|rad|-10)^2)
    float ema  = 0.0f;   // sum(relu(|atten|-1)^2)

    // ---- main stream: rad/tgt (213.9 MB), fused with rad EM term ----
    for (int v = tid; v < TOT4; v += stride) {
        const int s4   = v % S4;
        const int row  = v / S4;      // (b*U + u)*NBS + nbs
        const int arow = row / PNBS;  // b*U + u

        const float4 are = __ldg(&a_re_g[arow * S4 + s4]);
        const float4 aim = __ldg(&a_im_g[arow * S4 + s4]);
        const float4 rre = r_re_g[v];
        const float4 rim = r_im_g[v];
        const float4 tre = t_re_g[v];
        const float4 tim = t_im_g[v];
        const float4 wv  = __ldg(&w_g[s4]);

        #define PRISM_LANE(C)                                               \
        {                                                                   \
            float pr = fmaf(are.C, rre.C, -(aim.C * rim.C));                \
            float pi = fmaf(are.C, rim.C,  (aim.C * rre.C));                \
            float dr = pr - tre.C;                                          \
            float di = pi - tim.C;                                          \
            float se = fmaf(dr, dr, di * di);                               \
            recv = fmaf(se, wv.C, recv);                                    \
            float m2 = fmaf(rre.C, rre.C, rim.C * rim.C);                   \
            if (m2 > 100.0f) {                                              \
                float d = sqrtf(m2) - 10.0f;                                \
                emr = fmaf(d, d, emr);                                      \
            }                                                               \
        }
        PRISM_LANE(x) PRISM_LANE(y) PRISM_LANE(z) PRISM_LANE(w)
        #undef PRISM_LANE
    }

    // ---- small loop: atten EM term (0.84 MB x2, L2-resident) ----
    for (int v = tid; v < AT4; v += stride) {
        const float4 are = a_re_g[v];
        const float4 aim = a_im_g[v];
        #define ATTEN_LANE(C)                                               \
        {                                                                   \
            float m2 = fmaf(are.C, are.C, aim.C * aim.C);                   \
            if (m2 > 1.0f) {                                                \
                float d = sqrtf(m2) - 1.0f;                                 \
                ema = fmaf(d, d, ema);                                      \
            }                                                               \
        }
        ATTEN_LANE(x) ATTEN_LANE(y) ATTEN_LANE(z) ATTEN_LANE(w)
        #undef ATTEN_LANE
    }

    // ---- block reduce (warp shuffle + smem) ----
    __shared__ float s_recv[8], s_emr[8], s_ema[8];
    const int lane = threadIdx.x & 31;
    const int wid  = threadIdx.x >> 5;

    recv = warp_reduce(recv);
    emr  = warp_reduce(emr);
    ema  = warp_reduce(ema);
    if (lane == 0) { s_recv[wid] = recv; s_emr[wid] = emr; s_ema[wid] = ema; }
    __syncthreads();

    if (wid == 0) {
        recv = (lane < 8) ? s_recv[lane] : 0.0f;
        emr  = (lane < 8) ? s_emr[lane]  : 0.0f;
        ema  = (lane < 8) ? s_ema[lane]  : 0.0f;
        recv = warp_reduce(recv);
        emr  = warp_reduce(emr);
        ema  = warp_reduce(ema);
        if (lane == 0) {
            atomicAdd(&g_recv,   (double)recv);
            atomicAdd(&g_em_rad, (double)emr);
            atomicAdd(&g_em_at,  (double)ema);
        }
    }
}

__global__ void prism_finalize_kernel(float* __restrict__ out) {
    double em = g_em_at / (double)AT + g_em_rad / (double)TOT;
    out[0] = (float)(g_recv + 0.01 * em);
}

extern "C" void kernel_launch(void* const* d_in, const int* in_sizes, int n_in,
                              void* d_out, int out_size) {
    const float4* a_re = (const float4*)d_in[0];
    const float4* a_im = (const float4*)d_in[1];
    const float4* r_re = (const float4*)d_in[2];
    const float4* r_im = (const float4*)d_in[3];
    const float4* t_re = (const float4*)d_in[4];
    const float4* t_im = (const float4*)d_in[5];
    const float4* w    = (const float4*)d_in[6];
    // d_in[7..10]: positions / ue_positions / view_directions / bs_antenna_ids — unused.

    float* out = (float*)d_out;

    prism_init_kernel<<<1, 1>>>();
    prism_main_kernel<<<1184, 256>>>(a_re, a_im, r_re, r_im, t_re, t_im, w);
    prism_finalize_kernel<<<1, 1>>>(out);
}